// round 2
// baseline (speedup 1.0000x reference)
#include <cuda_runtime.h>
#include <math.h>

#define B_    32
#define C1    1024
#define N1    512
#define N2    256
#define HW    1024          // 32*32
#define NPIX  (B_*HW)       // 32768
#define IMG   512
#define RS    384
#define NREG  3

// ---------- scratch (static device globals; no runtime allocation) ----------
__device__ float g_h1[(size_t)NPIX * N1];   // 64 MB
__device__ float g_h2[(size_t)NPIX * N2];   // 32 MB
__device__ float g_att[NPIX];
__device__ int   g_xy[B_ * NREG * 2];       // (y1, x1) per region

// ---------------- fp32 tiled GEMM + bias + ReLU ----------------
// C[M=32768, N] = relu(A[M,K] * W[N,K]^T + bias)
// A_FEAT: A is features [B, C, 32, 32]  -> A[p,k] = A[b*C*HW + k*HW + hw], p=b*HW+hw
// else:   A row-major [M, K]
template <bool A_FEAT>
__global__ __launch_bounds__(256, 2)
void gemm_relu_kernel(const float* __restrict__ A, const float* __restrict__ W,
                      const float* __restrict__ bias, float* __restrict__ out,
                      int K, int N)
{
    __shared__ float As[16][128];
    __shared__ float Bs[16][128];

    const int tid = threadIdx.x;
    const int tx = tid & 15;          // 0..15 -> 8 cols each
    const int ty = tid >> 4;          // 0..15 -> 8 rows each
    const int rowBase = blockIdx.y * 128;
    const int colBase = blockIdx.x * 128;

    float acc[8][8];
#pragma unroll
    for (int i = 0; i < 8; i++)
#pragma unroll
        for (int j = 0; j < 8; j++) acc[i][j] = 0.f;

    for (int kt = 0; kt < K; kt += 16) {
        // ---- load A tile ----
        if (A_FEAT) {
            const int b0  = rowBase >> 10;
            const int hw0 = rowBase & 1023;
            const float* Ab = A + (size_t)b0 * ((size_t)C1 * HW) + hw0;
#pragma unroll
            for (int l = 0; l < 8; l++) {
                int idx = l * 256 + tid;
                int i  = idx & 127;
                int kk = idx >> 7;
                As[kk][i] = Ab[(size_t)(kt + kk) * HW + i];
            }
        } else {
            const int pp = tid >> 1;
            const int kh = (tid & 1) * 8;
            const float* ap = A + (size_t)(rowBase + pp) * K + kt + kh;
            float4 v0 = *(const float4*)ap;
            float4 v1 = *(const float4*)(ap + 4);
            As[kh + 0][pp] = v0.x; As[kh + 1][pp] = v0.y;
            As[kh + 2][pp] = v0.z; As[kh + 3][pp] = v0.w;
            As[kh + 4][pp] = v1.x; As[kh + 5][pp] = v1.y;
            As[kh + 6][pp] = v1.z; As[kh + 7][pp] = v1.w;
        }
        // ---- load W tile ----
        {
            const int oo = tid >> 1;
            const int kh = (tid & 1) * 8;
            const float* bp = W + (size_t)(colBase + oo) * K + kt + kh;
            float4 v0 = *(const float4*)bp;
            float4 v1 = *(const float4*)(bp + 4);
            Bs[kh + 0][oo] = v0.x; Bs[kh + 1][oo] = v0.y;
            Bs[kh + 2][oo] = v0.z; Bs[kh + 3][oo] = v0.w;
            Bs[kh + 4][oo] = v1.x; Bs[kh + 5][oo] = v1.y;
            Bs[kh + 6][oo] = v1.z; Bs[kh + 7][oo] = v1.w;
        }
        __syncthreads();

#pragma unroll
        for (int k = 0; k < 16; k++) {
            float4 a0 = *(const float4*)&As[k][ty * 8];
            float4 a1 = *(const float4*)&As[k][ty * 8 + 4];
            float4 b0 = *(const float4*)&Bs[k][tx * 8];
            float4 b1 = *(const float4*)&Bs[k][tx * 8 + 4];
            float ar[8] = {a0.x, a0.y, a0.z, a0.w, a1.x, a1.y, a1.z, a1.w};
            float br[8] = {b0.x, b0.y, b0.z, b0.w, b1.x, b1.y, b1.z, b1.w};
#pragma unroll
            for (int i = 0; i < 8; i++)
#pragma unroll
                for (int j = 0; j < 8; j++)
                    acc[i][j] = fmaf(ar[i], br[j], acc[i][j]);
        }
        __syncthreads();
    }

    // ---- epilogue: bias + relu ----
    const int col0 = colBase + tx * 8;
    float bb[8];
#pragma unroll
    for (int j = 0; j < 8; j++) bb[j] = bias[col0 + j];

    const int row0 = rowBase + ty * 8;
#pragma unroll
    for (int i = 0; i < 8; i++) {
        float4 o0, o1;
        o0.x = fmaxf(acc[i][0] + bb[0], 0.f);
        o0.y = fmaxf(acc[i][1] + bb[1], 0.f);
        o0.z = fmaxf(acc[i][2] + bb[2], 0.f);
        o0.w = fmaxf(acc[i][3] + bb[3], 0.f);
        o1.x = fmaxf(acc[i][4] + bb[4], 0.f);
        o1.y = fmaxf(acc[i][5] + bb[5], 0.f);
        o1.z = fmaxf(acc[i][6] + bb[6], 0.f);
        o1.w = fmaxf(acc[i][7] + bb[7], 0.f);
        float* op = out + (size_t)(row0 + i) * N + col0;
        *(float4*)op       = o0;
        *(float4*)(op + 4) = o1;
    }
}

// ---------------- layer 3 (matvec) + sigmoid + CAM average ----------------
__global__ void att_kernel(const float* __restrict__ h2, const float* __restrict__ w3,
                           const float* __restrict__ b3, const float* __restrict__ cam,
                           float* __restrict__ att_out)
{
    int warp = threadIdx.x >> 5;
    int lane = threadIdx.x & 31;
    int p = blockIdx.x * 8 + warp;
    const float* row = h2 + (size_t)p * N2;
    float s = 0.f;
#pragma unroll
    for (int j = 0; j < N2; j += 32) s = fmaf(row[j + lane], w3[j + lane], s);
#pragma unroll
    for (int off = 16; off; off >>= 1)
        s += __shfl_down_sync(0xffffffffu, s, off);
    if (lane == 0) {
        float v = 1.f / (1.f + expf(-(s + b3[0])));
        float a = (v + cam[p]) * 0.5f;
        g_att[p] = a;
        att_out[p] = a;
    }
}

// ---------------- peak picking: 1 block per batch ----------------
__global__ void peaks_kernel(float* __restrict__ coords_out)
{
    __shared__ float sm[1024];
    __shared__ float rv[8];
    __shared__ int   ri[8];
    __shared__ int   s_fy, s_fx;

    const int b = blockIdx.x;
    const int t = threadIdx.x;   // 256 threads

    for (int i = t; i < 1024; i += 256) sm[i] = g_att[b * 1024 + i];
    __syncthreads();

    for (int k = 0; k < NREG; k++) {
        float best = -1.f;
        int bi = 1 << 30;
        for (int i = t; i < 1024; i += 256) {
            float v = sm[i];
            if (v > best) { best = v; bi = i; }   // strided i increasing -> first max kept
        }
#pragma unroll
        for (int off = 16; off; off >>= 1) {
            float ov = __shfl_down_sync(0xffffffffu, best, off);
            int   oi = __shfl_down_sync(0xffffffffu, bi, off);
            if (ov > best || (ov == best && oi < bi)) { best = ov; bi = oi; }
        }
        if ((t & 31) == 0) { rv[t >> 5] = best; ri[t >> 5] = bi; }
        __syncthreads();
        if (t == 0) {
            for (int w = 1; w < 8; w++)
                if (rv[w] > best || (rv[w] == best && ri[w] < bi)) { best = rv[w]; bi = ri[w]; }
            int fy = bi >> 5, fx = bi & 31;
            if (!(best > 0.f)) { fy = 16; fx = 16; }
            int y1 = min(max(fy * 16 - (RS / 2), 0), IMG - RS);
            int x1 = min(max(fx * 16 - (RS / 2), 0), IMG - RS);
            int r = b * NREG + k;
            g_xy[r * 2 + 0] = y1;
            g_xy[r * 2 + 1] = x1;
            float* cp = coords_out + r * 4;
            cp[0] = (float)x1;
            cp[1] = (float)y1;
            cp[2] = (float)(x1 + RS);
            cp[3] = (float)(y1 + RS);
            s_fy = fy; s_fx = fx;
        }
        __syncthreads();
        int fy = s_fy, fx = s_fx;
        for (int i = t; i < 1024; i += 256) {
            int y = i >> 5, x = i & 31;
            if (abs(y - fy) <= 5 && abs(x - fx) <= 5) sm[i] = 0.f;
        }
        __syncthreads();
    }
}

// ---------------- region crops (memory-bound copy) ----------------
__global__ void crop_kernel(const float* __restrict__ orig, float* __restrict__ out)
{
    const int r = blockIdx.y;           // 0..95
    const int b = r / NREG;
    const int y1 = g_xy[r * 2 + 0];
    const int x1 = g_xy[r * 2 + 1];     // multiple of 16 -> float4 aligned

    int idx = blockIdx.x * blockDim.x + threadIdx.x;  // float4 index within region
    // region = 3 * 384 * 384 floats = 3*384*96 float4 = 110592
    int col4 = idx % 96;
    int tmp  = idx / 96;
    int row  = tmp % RS;
    int c    = tmp / RS;

    const float* src = orig + (((size_t)(b * 3 + c) * IMG) + (y1 + row)) * IMG + x1;
    float4 v = *((const float4*)src + col4);
    float4* dst = (float4*)(out + (size_t)r * (3 * RS * RS)) + idx;
    *dst = v;
}

// ---------------- launch ----------------
extern "C" void kernel_launch(void* const* d_in, const int* in_sizes, int n_in,
                              void* d_out, int out_size)
{
    const float* features = (const float*)d_in[0];
    const float* cam      = (const float*)d_in[1];
    const float* original = (const float*)d_in[2];
    const float* w1 = (const float*)d_in[3];
    const float* b1 = (const float*)d_in[4];
    const float* w2 = (const float*)d_in[5];
    const float* b2 = (const float*)d_in[6];
    const float* w3 = (const float*)d_in[7];
    const float* b3 = (const float*)d_in[8];

    float* out = (float*)d_out;
    const size_t regions_elems = (size_t)B_ * NREG * 3 * RS * RS;  // 42467328
    float* coords_out = out + regions_elems;                       // 384 floats
    float* att_out    = coords_out + (size_t)B_ * NREG * 4;        // 32768 floats

    float* h1;  cudaGetSymbolAddress((void**)&h1, g_h1);
    float* h2;  cudaGetSymbolAddress((void**)&h2, g_h2);

    // GEMM1: [32768,1024] x [512,1024]^T -> relu -> h1
    gemm_relu_kernel<true><<<dim3(N1 / 128, NPIX / 128), 256>>>(features, w1, b1, h1, C1, N1);
    // GEMM2: [32768,512] x [256,512]^T -> relu -> h2
    gemm_relu_kernel<false><<<dim3(N2 / 128, NPIX / 128), 256>>>(h1, w2, b2, h2, N1, N2);
    // layer3 + sigmoid + cam
    att_kernel<<<NPIX / 8, 256>>>(h2, w3, b3, cam, att_out);
    // peaks + coords
    peaks_kernel<<<B_, 256>>>(coords_out);
    // crops: 96 regions x 110592 float4
    crop_kernel<<<dim3(432, B_ * NREG), 256>>>(original, out);
}

// round 5
// speedup vs baseline: 1.4865x; 1.4865x over previous
#include <cuda_runtime.h>
#include <cuda_fp16.h>
#include <mma.h>
#include <cstdint>
#include <math.h>

using namespace nvcuda;

#define B_    32
#define C1    1024
#define N1    512
#define N2    256
#define HW    1024
#define NPIX  (B_*HW)
#define IMG   512
#define RS    384
#define NREG  3

// ---------------- static device scratch ----------------
__device__ __align__(16) __half g_a1h[(size_t)NPIX * C1];
__device__ __align__(16) __half g_a1l[(size_t)NPIX * C1];
__device__ __align__(16) __half g_h1h[(size_t)NPIX * N1];
__device__ __align__(16) __half g_h1l[(size_t)NPIX * N1];
__device__ float g_h2[(size_t)NPIX * N2];
__device__ __align__(16) __half g_w1h[N1 * C1];
__device__ __align__(16) __half g_w1l[N1 * C1];
__device__ __align__(16) __half g_w2h[N2 * N1];
__device__ __align__(16) __half g_w2l[N2 * N1];
__device__ float g_att[NPIX];
__device__ int   g_xy[B_ * NREG * 2];

// ---------------- PTX helpers ----------------
__device__ __forceinline__ uint32_t smem_u32(const void* p) {
    uint32_t a;
    asm("{ .reg .u64 t; cvta.to.shared.u64 t, %1; cvt.u32.u64 %0, t; }" : "=r"(a) : "l"(p));
    return a;
}
__device__ __forceinline__ void cp16(uint32_t dst, const void* src) {
    asm volatile("cp.async.cg.shared.global [%0], [%1], 16;" :: "r"(dst), "l"(src));
}
__device__ __forceinline__ void cp_commit() { asm volatile("cp.async.commit_group;" ::: "memory"); }
template<int N> __device__ __forceinline__ void cp_wait() { asm volatile("cp.async.wait_group %0;" :: "n"(N) : "memory"); }

// ---------------- prep: features transpose + fp16 split ----------------
__global__ void conv_feat(const float* __restrict__ f) {
    __shared__ float tile[32][33];
    int b = blockIdx.z, k0 = blockIdx.x * 32, hw0 = blockIdx.y * 32;
    int tx = threadIdx.x & 31, ty = threadIdx.x >> 5;   // 32 x 8
    const float* src = f + ((size_t)b << 20) + (size_t)k0 * 1024 + hw0;
#pragma unroll
    for (int r = 0; r < 4; r++)
        tile[ty + r * 8][tx] = src[(size_t)(ty + r * 8) * 1024 + tx];
    __syncthreads();
#pragma unroll
    for (int r = 0; r < 4; r++) {
        int hw = ty + r * 8;
        float v = tile[tx][hw];
        size_t o = (((size_t)b << 10) + hw0 + hw) * 1024 + k0 + tx;
        __half h = __float2half_rn(v);
        g_a1h[o] = h;
        g_a1l[o] = __float2half_rn(v - __half2float(h));
    }
}

__global__ void conv_w(const float* __restrict__ w, __half* __restrict__ oh,
                       __half* __restrict__ ol, int n) {
    int i = blockIdx.x * 256 + threadIdx.x;
    if (i < n) {
        float v = w[i];
        __half h = __float2half_rn(v);
        oh[i] = h;
        ol[i] = __float2half_rn(v - __half2float(h));
    }
}

// ---------------- wmma GEMM: C = relu(A*W^T + b), 3-term fp16 split ----------------
// CTA tile 128x128, BK=32 halfs, 3-stage cp.async pipeline.
#define STG_B   20480
#define LDH     40
#define LDS_    132
#define SMEM_DYN 67584

template<bool SPLIT>
__global__ __launch_bounds__(256, 1)
void gemm_hmma(const __half* __restrict__ a_h, const __half* __restrict__ a_l,
               const __half* __restrict__ b_h, const __half* __restrict__ b_l,
               const float* __restrict__ bias, int K, int Nout,
               __half* __restrict__ outh, __half* __restrict__ outl,
               float* __restrict__ outf)
{
    extern __shared__ char sm[];
    const int t = threadIdx.x;
    const int warp = t >> 5;
    const int warpM = warp >> 1, warpN = warp & 1;   // 4 x 2 warps, tile 32 x 64
    const int mBase = blockIdx.y * 128, nBase = blockIdx.x * 128;

    const int KC  = K >> 5;
    const int NIT = 3 * KC;

    const __half* Ap[3] = {a_h, a_l, a_h};
    const __half* Bp[3] = {b_h, b_h, b_l};

    const uint32_t sbase = smem_u32(sm);

    wmma::fragment<wmma::accumulator, 16, 16, 16, float> acc[2][4];
#pragma unroll
    for (int i = 0; i < 2; i++)
#pragma unroll
        for (int j = 0; j < 4; j++)
            wmma::fill_fragment(acc[i][j], 0.f);

    // per stage: A = 128 rows x 32 halves = 512 16B-chunks, B same.
    // 256 threads -> each issues 2 chunks for A and 2 for B.
    auto issue = [&](int kk) {
        const int term = kk / KC;
        const int kc = (kk % KC) << 5;
        const int s = kk % 3;
        const __half* At = Ap[term];
        const __half* Bt = Bp[term];
#pragma unroll
        for (int u = 0; u < 2; u++) {
            int i = u * 256 + t;             // 0..511
            int row = i >> 2, ch = i & 3;
            uint32_t off = (uint32_t)(row * LDH + ch * 8) * 2;
            cp16(sbase + s * STG_B + off,
                 At + (size_t)(mBase + row) * K + kc + ch * 8);
            cp16(sbase + s * STG_B + 10240u + off,
                 Bt + (size_t)(nBase + row) * K + kc + ch * 8);
        }
    };

    issue(0); cp_commit();
    issue(1); cp_commit();

    for (int kk = 0; kk < NIT; kk++) {
        const int s = kk % 3;
        cp_wait<1>();
        __syncthreads();
        const __half* As = (const __half*)(sm + s * STG_B);
        const __half* Bs = (const __half*)(sm + s * STG_B + 10240);

        wmma::fragment<wmma::matrix_a, 16, 16, 16, __half, wmma::row_major> af[2];
        wmma::fragment<wmma::matrix_b, 16, 16, 16, __half, wmma::col_major> bf[4];
#pragma unroll
        for (int k16 = 0; k16 < 2; k16++) {
            wmma::load_matrix_sync(af[0], As + (warpM * 32) * LDH + k16 * 16, LDH);
            wmma::load_matrix_sync(af[1], As + (warpM * 32 + 16) * LDH + k16 * 16, LDH);
#pragma unroll
            for (int j = 0; j < 4; j++)
                wmma::load_matrix_sync(bf[j], Bs + (warpN * 64 + j * 16) * LDH + k16 * 16, LDH);
#pragma unroll
            for (int i = 0; i < 2; i++)
#pragma unroll
                for (int j = 0; j < 4; j++)
                    wmma::mma_sync(acc[i][j], af[i], bf[j], acc[i][j]);
        }
        if (kk + 2 < NIT) issue(kk + 2);
        cp_commit();
    }

    __syncthreads();
    float* stg = (float*)sm;
#pragma unroll
    for (int i = 0; i < 2; i++)
#pragma unroll
        for (int j = 0; j < 4; j++)
            wmma::store_matrix_sync(stg + (warpM * 32 + i * 16) * LDS_ + warpN * 64 + j * 16,
                                    acc[i][j], LDS_, wmma::mem_row_major);
    __syncthreads();

    if (SPLIT) {
#pragma unroll
        for (int it = 0; it < 32; it++) {
            int i = it * 256 + t;            // half2 index, 8192 total
            int lr = i >> 6, lc = (i & 63) << 1;
            float v0 = fmaxf(stg[lr * LDS_ + lc]     + bias[nBase + lc],     0.f);
            float v1 = fmaxf(stg[lr * LDS_ + lc + 1] + bias[nBase + lc + 1], 0.f);
            __half h0 = __float2half_rn(v0), h1 = __float2half_rn(v1);
            __half l0 = __float2half_rn(v0 - __half2float(h0));
            __half l1 = __float2half_rn(v1 - __half2float(h1));
            size_t o = (size_t)(mBase + lr) * Nout + nBase + lc;
            *(__half2*)(outh + o) = __halves2half2(h0, h1);
            *(__half2*)(outl + o) = __halves2half2(l0, l1);
        }
    } else {
#pragma unroll
        for (int it = 0; it < 64; it++) {
            int i = it * 256 + t;            // f32 index, 16384 total
            int lr = i >> 7, lc = i & 127;
            float v = stg[lr * LDS_ + lc] + bias[nBase + lc];
            outf[(size_t)(mBase + lr) * Nout + nBase + lc] = fmaxf(v, 0.f);
        }
    }
}

// ---------------- layer 3 matvec + sigmoid + CAM ----------------
__global__ void att_kernel(const float* __restrict__ w3, const float* __restrict__ b3,
                           const float* __restrict__ cam, float* __restrict__ att_out)
{
    int warp = threadIdx.x >> 5;
    int lane = threadIdx.x & 31;
    int p = blockIdx.x * 8 + warp;
    const float* rowp = g_h2 + (size_t)p * N2;
    float s = 0.f;
#pragma unroll
    for (int j = 0; j < N2; j += 32) s = fmaf(rowp[j + lane], w3[j + lane], s);
#pragma unroll
    for (int off = 16; off; off >>= 1)
        s += __shfl_down_sync(0xffffffffu, s, off);
    if (lane == 0) {
        float v = 1.f / (1.f + expf(-(s + b3[0])));
        float a = (v + cam[p]) * 0.5f;
        g_att[p] = a;
        att_out[p] = a;
    }
}

// ---------------- peak picking ----------------
__global__ void peaks_kernel(float* __restrict__ coords_out)
{
    __shared__ float smv[1024];
    __shared__ float rv[8];
    __shared__ int   ri[8];
    __shared__ int   s_fy, s_fx;

    const int b = blockIdx.x;
    const int t = threadIdx.x;

    for (int i = t; i < 1024; i += 256) smv[i] = g_att[b * 1024 + i];
    __syncthreads();

    for (int k = 0; k < NREG; k++) {
        float best = -1.f;
        int bi = 1 << 30;
        for (int i = t; i < 1024; i += 256) {
            float v = smv[i];
            if (v > best) { best = v; bi = i; }
        }
#pragma unroll
        for (int off = 16; off; off >>= 1) {
            float ov = __shfl_down_sync(0xffffffffu, best, off);
            int   oi = __shfl_down_sync(0xffffffffu, bi, off);
            if (ov > best || (ov == best && oi < bi)) { best = ov; bi = oi; }
        }
        if ((t & 31) == 0) { rv[t >> 5] = best; ri[t >> 5] = bi; }
        __syncthreads();
        if (t == 0) {
            for (int w = 1; w < 8; w++)
                if (rv[w] > best || (rv[w] == best && ri[w] < bi)) { best = rv[w]; bi = ri[w]; }
            int fy = bi >> 5, fx = bi & 31;
            if (!(best > 0.f)) { fy = 16; fx = 16; }
            int y1 = min(max(fy * 16 - (RS / 2), 0), IMG - RS);
            int x1 = min(max(fx * 16 - (RS / 2), 0), IMG - RS);
            int r = b * NREG + k;
            g_xy[r * 2 + 0] = y1;
            g_xy[r * 2 + 1] = x1;
            float* cp = coords_out + r * 4;
            cp[0] = (float)x1;
            cp[1] = (float)y1;
            cp[2] = (float)(x1 + RS);
            cp[3] = (float)(y1 + RS);
            s_fy = fy; s_fx = fx;
        }
        __syncthreads();
        int fy = s_fy, fx = s_fx;
        for (int i = t; i < 1024; i += 256) {
            int y = i >> 5, x = i & 31;
            if (abs(y - fy) <= 5 && abs(x - fx) <= 5) smv[i] = 0.f;
        }
        __syncthreads();
    }
}

// ---------------- region crops ----------------
__global__ void crop_kernel(const float* __restrict__ orig, float* __restrict__ out)
{
    const int r = blockIdx.y;
    const int b = r / NREG;
    const int y1 = g_xy[r * 2 + 0];
    const int x1 = g_xy[r * 2 + 1];

    int idx = blockIdx.x * blockDim.x + threadIdx.x;
    int col4 = idx % 96;
    int tmp  = idx / 96;
    int rrow = tmp % RS;
    int c    = tmp / RS;

    const float* src = orig + (((size_t)(b * 3 + c) * IMG) + (y1 + rrow)) * IMG + x1;
    float4 v = *((const float4*)src + col4);
    float4* dst = (float4*)(out + (size_t)r * (3 * RS * RS)) + idx;
    *dst = v;
}

// ---------------- launch ----------------
extern "C" void kernel_launch(void* const* d_in, const int* in_sizes, int n_in,
                              void* d_out, int out_size)
{
    const float* features = (const float*)d_in[0];
    const float* cam      = (const float*)d_in[1];
    const float* original = (const float*)d_in[2];
    const float* w1 = (const float*)d_in[3];
    const float* b1 = (const float*)d_in[4];
    const float* w2 = (const float*)d_in[5];
    const float* b2 = (const float*)d_in[6];
    const float* w3 = (const float*)d_in[7];
    const float* b3 = (const float*)d_in[8];

    float* out = (float*)d_out;
    const size_t regions_elems = (size_t)B_ * NREG * 3 * RS * RS;
    float* coords_out = out + regions_elems;
    float* att_out    = coords_out + (size_t)B_ * NREG * 4;

    __half *a1h, *a1l, *h1h, *h1l, *w1h, *w1l, *w2h, *w2l;
    float *h2;
    cudaGetSymbolAddress((void**)&a1h, g_a1h);
    cudaGetSymbolAddress((void**)&a1l, g_a1l);
    cudaGetSymbolAddress((void**)&h1h, g_h1h);
    cudaGetSymbolAddress((void**)&h1l, g_h1l);
    cudaGetSymbolAddress((void**)&w1h, g_w1h);
    cudaGetSymbolAddress((void**)&w1l, g_w1l);
    cudaGetSymbolAddress((void**)&w2h, g_w2h);
    cudaGetSymbolAddress((void**)&w2l, g_w2l);
    cudaGetSymbolAddress((void**)&h2,  g_h2);

    cudaFuncSetAttribute(gemm_hmma<true>,  cudaFuncAttributeMaxDynamicSharedMemorySize, SMEM_DYN);
    cudaFuncSetAttribute(gemm_hmma<false>, cudaFuncAttributeMaxDynamicSharedMemorySize, SMEM_DYN);

    conv_feat<<<dim3(32, 32, 32), 256>>>(features);
    conv_w<<<(N1 * C1 + 255) / 256, 256>>>(w1, w1h, w1l, N1 * C1);
    conv_w<<<(N2 * N1 + 255) / 256, 256>>>(w2, w2h, w2l, N2 * N1);

    // GEMM1: relu(features x w1^T + b1) -> h1 (fp16 split out)
    gemm_hmma<true><<<dim3(N1 / 128, NPIX / 128), 256, SMEM_DYN>>>(
        a1h, a1l, w1h, w1l, b1, C1, N1, h1h, h1l, nullptr);
    // GEMM2: relu(h1 x w2^T + b2) -> h2 (f32 out)
    gemm_hmma<false><<<dim3(N2 / 128, NPIX / 128), 256, SMEM_DYN>>>(
        h1h, h1l, w2h, w2l, b2, N1, N2, nullptr, nullptr, h2);

    att_kernel<<<NPIX / 8, 256>>>(w3, b3, cam, att_out);
    peaks_kernel<<<B_, 256>>>(coords_out);
    crop_kernel<<<dim3(432, B_ * NREG), 256>>>(original, out);
}

// round 6
// speedup vs baseline: 1.7398x; 1.1704x over previous
#include <cuda_runtime.h>
#include <cuda_fp16.h>
#include <mma.h>
#include <cstdint>
#include <math.h>

using namespace nvcuda;

#define B_    32
#define C1    1024
#define N1    512
#define N2    256
#define HW    1024
#define NPIX  (B_*HW)
#define IMG   512
#define RS    384
#define NREG  3

// ---------------- static device scratch ----------------
__device__ __align__(16) __half g_a1h[(size_t)NPIX * C1];
__device__ __align__(16) __half g_a1l[(size_t)NPIX * C1];
__device__ __align__(16) __half g_h1h[(size_t)NPIX * N1];
__device__ __align__(16) __half g_h1l[(size_t)NPIX * N1];
__device__ float g_h2[(size_t)NPIX * N2];
__device__ __align__(16) __half g_w1h[N1 * C1];
__device__ __align__(16) __half g_w1l[N1 * C1];
__device__ __align__(16) __half g_w2h[N2 * N1];
__device__ __align__(16) __half g_w2l[N2 * N1];
__device__ float g_att[NPIX];
__device__ int   g_xy[B_ * NREG * 2];

// ---------------- PTX helpers ----------------
__device__ __forceinline__ uint32_t smem_u32(const void* p) {
    uint32_t a;
    asm("{ .reg .u64 t; cvta.to.shared.u64 t, %1; cvt.u32.u64 %0, t; }" : "=r"(a) : "l"(p));
    return a;
}
__device__ __forceinline__ void cp16(uint32_t dst, const void* src) {
    asm volatile("cp.async.cg.shared.global [%0], [%1], 16;" :: "r"(dst), "l"(src));
}
__device__ __forceinline__ void cp_commit() { asm volatile("cp.async.commit_group;" ::: "memory"); }
template<int N> __device__ __forceinline__ void cp_wait() { asm volatile("cp.async.wait_group %0;" :: "n"(N) : "memory"); }

// ---------------- prep: features transpose + fp16 split ----------------
__global__ void conv_feat(const float* __restrict__ f) {
    __shared__ float tile[32][33];
    int b = blockIdx.z, k0 = blockIdx.x * 32, hw0 = blockIdx.y * 32;
    int tx = threadIdx.x & 31, ty = threadIdx.x >> 5;   // 32 x 8
    const float* src = f + ((size_t)b << 20) + (size_t)k0 * 1024 + hw0;
#pragma unroll
    for (int r = 0; r < 4; r++)
        tile[ty + r * 8][tx] = src[(size_t)(ty + r * 8) * 1024 + tx];
    __syncthreads();
#pragma unroll
    for (int r = 0; r < 4; r++) {
        int hw = ty + r * 8;
        float v = tile[tx][hw];
        size_t o = (((size_t)b << 10) + hw0 + hw) * 1024 + k0 + tx;
        __half h = __float2half_rn(v);
        g_a1h[o] = h;
        g_a1l[o] = __float2half_rn(v - __half2float(h));
    }
}

__global__ void conv_w(const float* __restrict__ w, __half* __restrict__ oh,
                       __half* __restrict__ ol, int n) {
    int i = blockIdx.x * 256 + threadIdx.x;
    if (i < n) {
        float v = w[i];
        __half h = __float2half_rn(v);
        oh[i] = h;
        ol[i] = __float2half_rn(v - __half2float(h));
    }
}

// ---------------- wmma GEMM: C = relu(A*W^T + b), 3-term fp16 split ----------------
// CTA tile 128x128, 512 threads (16 warps, warp tile 32x32), BK=32, 4-stage cp.async.
#define STG_B   20480
#define LDH     40
#define LDS_    132
#define SMEM_DYN (4*STG_B)   // 81920

template<bool SPLIT>
__global__ __launch_bounds__(512, 2)
void gemm_hmma(const __half* __restrict__ a_h, const __half* __restrict__ a_l,
               const __half* __restrict__ b_h, const __half* __restrict__ b_l,
               const float* __restrict__ bias, int K, int Nout,
               __half* __restrict__ outh, __half* __restrict__ outl,
               float* __restrict__ outf)
{
    extern __shared__ char sm[];
    const int t = threadIdx.x;
    const int warp = t >> 5;
    const int warpM = warp >> 2, warpN = warp & 3;   // 4 x 4 warps, each 32 x 32
    const int mBase = blockIdx.y * 128, nBase = blockIdx.x * 128;

    const int KC  = K >> 5;
    const int NIT = 3 * KC;

    const __half* Ap[3] = {a_h, a_l, a_h};
    const __half* Bp[3] = {b_h, b_h, b_l};

    const uint32_t sbase = smem_u32(sm);

    wmma::fragment<wmma::accumulator, 16, 16, 16, float> acc[2][2];
#pragma unroll
    for (int i = 0; i < 2; i++)
#pragma unroll
        for (int j = 0; j < 2; j++)
            wmma::fill_fragment(acc[i][j], 0.f);

    // per stage: A = 128 rows x 32 halves = 512 16B-chunks; B same.
    // 512 threads -> each issues 1 chunk for A and 1 for B.
    auto issue = [&](int kk) {
        const int term = kk / KC;
        const int kc = (kk % KC) << 5;
        const int s = kk & 3;
        const int row = t >> 2, ch = t & 3;
        uint32_t off = (uint32_t)(row * LDH + ch * 8) * 2;
        cp16(sbase + s * STG_B + off,
             Ap[term] + (size_t)(mBase + row) * K + kc + ch * 8);
        cp16(sbase + s * STG_B + 10240u + off,
             Bp[term] + (size_t)(nBase + row) * K + kc + ch * 8);
    };

    issue(0); cp_commit();
    issue(1); cp_commit();
    issue(2); cp_commit();

    for (int kk = 0; kk < NIT; kk++) {
        const int s = kk & 3;
        cp_wait<2>();
        __syncthreads();
        const __half* As = (const __half*)(sm + s * STG_B);
        const __half* Bs = (const __half*)(sm + s * STG_B + 10240);

        wmma::fragment<wmma::matrix_a, 16, 16, 16, __half, wmma::row_major> af[2];
        wmma::fragment<wmma::matrix_b, 16, 16, 16, __half, wmma::col_major> bf[2];
#pragma unroll
        for (int k16 = 0; k16 < 2; k16++) {
            wmma::load_matrix_sync(af[0], As + (warpM * 32) * LDH + k16 * 16, LDH);
            wmma::load_matrix_sync(af[1], As + (warpM * 32 + 16) * LDH + k16 * 16, LDH);
            wmma::load_matrix_sync(bf[0], Bs + (warpN * 32) * LDH + k16 * 16, LDH);
            wmma::load_matrix_sync(bf[1], Bs + (warpN * 32 + 16) * LDH + k16 * 16, LDH);
#pragma unroll
            for (int i = 0; i < 2; i++)
#pragma unroll
                for (int j = 0; j < 2; j++)
                    wmma::mma_sync(acc[i][j], af[i], bf[j], acc[i][j]);
        }
        if (kk + 3 < NIT) issue(kk + 3);
        cp_commit();
    }

    __syncthreads();
    float* stg = (float*)sm;
#pragma unroll
    for (int i = 0; i < 2; i++)
#pragma unroll
        for (int j = 0; j < 2; j++)
            wmma::store_matrix_sync(stg + (warpM * 32 + i * 16) * LDS_ + warpN * 32 + j * 16,
                                    acc[i][j], LDS_, wmma::mem_row_major);
    __syncthreads();

    if (SPLIT) {
#pragma unroll
        for (int it = 0; it < 16; it++) {
            int i = it * 512 + t;            // half2 index, 8192 total
            int lr = i >> 6, lc = (i & 63) << 1;
            float v0 = fmaxf(stg[lr * LDS_ + lc]     + bias[nBase + lc],     0.f);
            float v1 = fmaxf(stg[lr * LDS_ + lc + 1] + bias[nBase + lc + 1], 0.f);
            __half h0 = __float2half_rn(v0), h1 = __float2half_rn(v1);
            __half l0 = __float2half_rn(v0 - __half2float(h0));
            __half l1 = __float2half_rn(v1 - __half2float(h1));
            size_t o = (size_t)(mBase + lr) * Nout + nBase + lc;
            *(__half2*)(outh + o) = __halves2half2(h0, h1);
            *(__half2*)(outl + o) = __halves2half2(l0, l1);
        }
    } else {
#pragma unroll
        for (int it = 0; it < 32; it++) {
            int i = it * 512 + t;            // f32 index, 16384 total
            int lr = i >> 7, lc = i & 127;
            float v = stg[lr * LDS_ + lc] + bias[nBase + lc];
            outf[(size_t)(mBase + lr) * Nout + nBase + lc] = fmaxf(v, 0.f);
        }
    }
}

// ---------------- layer 3 matvec + sigmoid + CAM ----------------
__global__ void att_kernel(const float* __restrict__ w3, const float* __restrict__ b3,
                           const float* __restrict__ cam, float* __restrict__ att_out)
{
    int warp = threadIdx.x >> 5;
    int lane = threadIdx.x & 31;
    int p = blockIdx.x * 8 + warp;
    const float* rowp = g_h2 + (size_t)p * N2;
    float s = 0.f;
#pragma unroll
    for (int j = 0; j < N2; j += 32) s = fmaf(rowp[j + lane], w3[j + lane], s);
#pragma unroll
    for (int off = 16; off; off >>= 1)
        s += __shfl_down_sync(0xffffffffu, s, off);
    if (lane == 0) {
        float v = 1.f / (1.f + expf(-(s + b3[0])));
        float a = (v + cam[p]) * 0.5f;
        g_att[p] = a;
        att_out[p] = a;
    }
}

// ---------------- peak picking ----------------
__global__ void peaks_kernel(float* __restrict__ coords_out)
{
    __shared__ float smv[1024];
    __shared__ float rv[8];
    __shared__ int   ri[8];
    __shared__ int   s_fy, s_fx;

    const int b = blockIdx.x;
    const int t = threadIdx.x;

    for (int i = t; i < 1024; i += 256) smv[i] = g_att[b * 1024 + i];
    __syncthreads();

    for (int k = 0; k < NREG; k++) {
        float best = -1.f;
        int bi = 1 << 30;
        for (int i = t; i < 1024; i += 256) {
            float v = smv[i];
            if (v > best) { best = v; bi = i; }
        }
#pragma unroll
        for (int off = 16; off; off >>= 1) {
            float ov = __shfl_down_sync(0xffffffffu, best, off);
            int   oi = __shfl_down_sync(0xffffffffu, bi, off);
            if (ov > best || (ov == best && oi < bi)) { best = ov; bi = oi; }
        }
        if ((t & 31) == 0) { rv[t >> 5] = best; ri[t >> 5] = bi; }
        __syncthreads();
        if (t == 0) {
            for (int w = 1; w < 8; w++)
                if (rv[w] > best || (rv[w] == best && ri[w] < bi)) { best = rv[w]; bi = ri[w]; }
            int fy = bi >> 5, fx = bi & 31;
            if (!(best > 0.f)) { fy = 16; fx = 16; }
            int y1 = min(max(fy * 16 - (RS / 2), 0), IMG - RS);
            int x1 = min(max(fx * 16 - (RS / 2), 0), IMG - RS);
            int r = b * NREG + k;
            g_xy[r * 2 + 0] = y1;
            g_xy[r * 2 + 1] = x1;
            float* cp = coords_out + r * 4;
            cp[0] = (float)x1;
            cp[1] = (float)y1;
            cp[2] = (float)(x1 + RS);
            cp[3] = (float)(y1 + RS);
            s_fy = fy; s_fx = fx;
        }
        __syncthreads();
        int fy = s_fy, fx = s_fx;
        for (int i = t; i < 1024; i += 256) {
            int y = i >> 5, x = i & 31;
            if (abs(y - fy) <= 5 && abs(x - fx) <= 5) smv[i] = 0.f;
        }
        __syncthreads();
    }
}

// ---------------- region crops ----------------
__global__ void crop_kernel(const float* __restrict__ orig, float* __restrict__ out)
{
    const int r = blockIdx.y;
    const int b = r / NREG;
    const int y1 = g_xy[r * 2 + 0];
    const int x1 = g_xy[r * 2 + 1];

    int idx = blockIdx.x * blockDim.x + threadIdx.x;
    int col4 = idx % 96;
    int tmp  = idx / 96;
    int rrow = tmp % RS;
    int c    = tmp / RS;

    const float* src = orig + (((size_t)(b * 3 + c) * IMG) + (y1 + rrow)) * IMG + x1;
    float4 v = *((const float4*)src + col4);
    float4* dst = (float4*)(out + (size_t)r * (3 * RS * RS)) + idx;
    *dst = v;
}

// ---------------- launch ----------------
extern "C" void kernel_launch(void* const* d_in, const int* in_sizes, int n_in,
                              void* d_out, int out_size)
{
    const float* features = (const float*)d_in[0];
    const float* cam      = (const float*)d_in[1];
    const float* original = (const float*)d_in[2];
    const float* w1 = (const float*)d_in[3];
    const float* b1 = (const float*)d_in[4];
    const float* w2 = (const float*)d_in[5];
    const float* b2 = (const float*)d_in[6];
    const float* w3 = (const float*)d_in[7];
    const float* b3 = (const float*)d_in[8];

    float* out = (float*)d_out;
    const size_t regions_elems = (size_t)B_ * NREG * 3 * RS * RS;
    float* coords_out = out + regions_elems;
    float* att_out    = coords_out + (size_t)B_ * NREG * 4;

    __half *a1h, *a1l, *h1h, *h1l, *w1h, *w1l, *w2h, *w2l;
    float *h2;
    cudaGetSymbolAddress((void**)&a1h, g_a1h);
    cudaGetSymbolAddress((void**)&a1l, g_a1l);
    cudaGetSymbolAddress((void**)&h1h, g_h1h);
    cudaGetSymbolAddress((void**)&h1l, g_h1l);
    cudaGetSymbolAddress((void**)&w1h, g_w1h);
    cudaGetSymbolAddress((void**)&w1l, g_w1l);
    cudaGetSymbolAddress((void**)&w2h, g_w2h);
    cudaGetSymbolAddress((void**)&w2l, g_w2l);
    cudaGetSymbolAddress((void**)&h2,  g_h2);

    cudaFuncSetAttribute(gemm_hmma<true>,  cudaFuncAttributeMaxDynamicSharedMemorySize, SMEM_DYN);
    cudaFuncSetAttribute(gemm_hmma<false>, cudaFuncAttributeMaxDynamicSharedMemorySize, SMEM_DYN);

    conv_feat<<<dim3(32, 32, 32), 256>>>(features);
    conv_w<<<(N1 * C1 + 255) / 256, 256>>>(w1, w1h, w1l, N1 * C1);
    conv_w<<<(N2 * N1 + 255) / 256, 256>>>(w2, w2h, w2l, N2 * N1);

    // GEMM1: relu(features x w1^T + b1) -> h1 (fp16 split out)
    gemm_hmma<true><<<dim3(N1 / 128, NPIX / 128), 512, SMEM_DYN>>>(
        a1h, a1l, w1h, w1l, b1, C1, N1, h1h, h1l, nullptr);
    // GEMM2: relu(h1 x w2^T + b2) -> h2 (f32 out)
    gemm_hmma<false><<<dim3(N2 / 128, NPIX / 128), 512, SMEM_DYN>>>(
        h1h, h1l, w2h, w2l, b2, N1, N2, nullptr, nullptr, h2);

    att_kernel<<<NPIX / 8, 256>>>(w3, b3, cam, att_out);
    peaks_kernel<<<B_, 256>>>(coords_out);
    crop_kernel<<<dim3(432, B_ * NREG), 256>>>(original, out);
}

// round 7
// speedup vs baseline: 2.0821x; 1.1968x over previous
#include <cuda_runtime.h>
#include <cuda_fp16.h>
#include <mma.h>
#include <cstdint>
#include <math.h>

using namespace nvcuda;

#define B_    32
#define C1    1024
#define N1    512
#define N2    256
#define HW    1024
#define NPIX  (B_*HW)
#define IMG   512
#define RS    384
#define NREG  3

// ---------------- static device scratch ----------------
__device__ __align__(16) __half g_a1h[(size_t)NPIX * C1];
__device__ __align__(16) __half g_a1l[(size_t)NPIX * C1];
__device__ __align__(16) __half g_h1h[(size_t)NPIX * N1];
__device__ __align__(16) __half g_h1l[(size_t)NPIX * N1];
__device__ float g_h2[(size_t)NPIX * N2];
__device__ __align__(16) __half g_w1h[N1 * C1];
__device__ __align__(16) __half g_w1l[N1 * C1];
__device__ __align__(16) __half g_w2h[N2 * N1];
__device__ __align__(16) __half g_w2l[N2 * N1];
__device__ float g_att[NPIX];
__device__ int   g_xy[B_ * NREG * 2];

// ---------------- PTX helpers ----------------
__device__ __forceinline__ uint32_t smem_u32(const void* p) {
    uint32_t a;
    asm("{ .reg .u64 t; cvta.to.shared.u64 t, %1; cvt.u32.u64 %0, t; }" : "=r"(a) : "l"(p));
    return a;
}
__device__ __forceinline__ void cp16(uint32_t dst, const void* src) {
    asm volatile("cp.async.cg.shared.global [%0], [%1], 16;" :: "r"(dst), "l"(src));
}
__device__ __forceinline__ void cp_commit() { asm volatile("cp.async.commit_group;" ::: "memory"); }
template<int N> __device__ __forceinline__ void cp_wait() { asm volatile("cp.async.wait_group %0;" :: "n"(N) : "memory"); }

// ---------------- prep: features transpose + fp16 split ----------------
__global__ void conv_feat(const float* __restrict__ f) {
    __shared__ float tile[32][33];
    int b = blockIdx.z, k0 = blockIdx.x * 32, hw0 = blockIdx.y * 32;
    int tx = threadIdx.x & 31, ty = threadIdx.x >> 5;   // 32 x 8
    const float* src = f + ((size_t)b << 20) + (size_t)k0 * 1024 + hw0;
#pragma unroll
    for (int r = 0; r < 4; r++)
        tile[ty + r * 8][tx] = src[(size_t)(ty + r * 8) * 1024 + tx];
    __syncthreads();
#pragma unroll
    for (int r = 0; r < 4; r++) {
        int hw = ty + r * 8;
        float v = tile[tx][hw];
        size_t o = (((size_t)b << 10) + hw0 + hw) * 1024 + k0 + tx;
        __half h = __float2half_rn(v);
        g_a1h[o] = h;
        g_a1l[o] = __float2half_rn(v - __half2float(h));
    }
}

__global__ void conv_w(const float* __restrict__ w, __half* __restrict__ oh,
                       __half* __restrict__ ol, int n) {
    int i = blockIdx.x * 256 + threadIdx.x;
    if (i < n) {
        float v = w[i];
        __half h = __float2half_rn(v);
        oh[i] = h;
        ol[i] = __float2half_rn(v - __half2float(h));
    }
}

// ---------------- wmma GEMM: C = relu(A*W^T + b), 3-term fp16 split ----------------
// CTA tile 128x128, 256 threads (8 warps, 4x2, warp tile 32x64), BK=32, 4-stage cp.async.
#define STG_B   20480
#define LDH     40
#define LDS_    132
#define SMEM_DYN (4*STG_B)   // 81920

template<bool SPLIT>
__global__ __launch_bounds__(256, 2)
void gemm_hmma(const __half* __restrict__ a_h, const __half* __restrict__ a_l,
               const __half* __restrict__ b_h, const __half* __restrict__ b_l,
               const float* __restrict__ bias, int K, int Nout,
               __half* __restrict__ outh, __half* __restrict__ outl,
               float* __restrict__ outf)
{
    extern __shared__ char sm[];
    const int t = threadIdx.x;
    const int warp = t >> 5;
    const int warpM = warp >> 1, warpN = warp & 1;   // 4 x 2 warps, each 32 x 64
    const int mBase = blockIdx.y * 128, nBase = blockIdx.x * 128;

    const int KC  = K >> 5;
    const int NIT = 3 * KC;

    const __half* Ap[3] = {a_h, a_l, a_h};
    const __half* Bp[3] = {b_h, b_h, b_l};

    const uint32_t sbase = smem_u32(sm);

    wmma::fragment<wmma::accumulator, 16, 16, 16, float> acc[2][4];
#pragma unroll
    for (int i = 0; i < 2; i++)
#pragma unroll
        for (int j = 0; j < 4; j++)
            wmma::fill_fragment(acc[i][j], 0.f);

    // per stage: A = 128 rows x 32 halves = 512 16B-chunks; B same.
    // 256 threads -> each issues 2 chunks for A and 2 for B.
    auto issue = [&](int kk) {
        const int term = kk / KC;
        const int kc = (kk % KC) << 5;
        const int s = kk & 3;
        const __half* At = Ap[term];
        const __half* Bt = Bp[term];
#pragma unroll
        for (int u = 0; u < 2; u++) {
            int i = u * 256 + t;             // 0..511
            int row = i >> 2, ch = i & 3;
            uint32_t off = (uint32_t)(row * LDH + ch * 8) * 2;
            cp16(sbase + s * STG_B + off,
                 At + (size_t)(mBase + row) * K + kc + ch * 8);
            cp16(sbase + s * STG_B + 10240u + off,
                 Bt + (size_t)(nBase + row) * K + kc + ch * 8);
        }
    };

    issue(0); cp_commit();
    issue(1); cp_commit();
    issue(2); cp_commit();

    for (int kk = 0; kk < NIT; kk++) {
        const int s = kk & 3;
        cp_wait<2>();
        __syncthreads();
        const __half* As = (const __half*)(sm + s * STG_B);
        const __half* Bs = (const __half*)(sm + s * STG_B + 10240);

        wmma::fragment<wmma::matrix_a, 16, 16, 16, __half, wmma::row_major> af[2];
#pragma unroll
        for (int k16 = 0; k16 < 2; k16++) {
            wmma::load_matrix_sync(af[0], As + (warpM * 32) * LDH + k16 * 16, LDH);
            wmma::load_matrix_sync(af[1], As + (warpM * 32 + 16) * LDH + k16 * 16, LDH);
#pragma unroll
            for (int j = 0; j < 4; j++) {
                wmma::fragment<wmma::matrix_b, 16, 16, 16, __half, wmma::col_major> bf;
                wmma::load_matrix_sync(bf, Bs + (warpN * 64 + j * 16) * LDH + k16 * 16, LDH);
                wmma::mma_sync(acc[0][j], af[0], bf, acc[0][j]);
                wmma::mma_sync(acc[1][j], af[1], bf, acc[1][j]);
            }
        }
        if (kk + 3 < NIT) issue(kk + 3);
        cp_commit();
    }

    __syncthreads();
    float* stg = (float*)sm;
#pragma unroll
    for (int i = 0; i < 2; i++)
#pragma unroll
        for (int j = 0; j < 4; j++)
            wmma::store_matrix_sync(stg + (warpM * 32 + i * 16) * LDS_ + warpN * 64 + j * 16,
                                    acc[i][j], LDS_, wmma::mem_row_major);
    __syncthreads();

    if (SPLIT) {
#pragma unroll
        for (int it = 0; it < 32; it++) {
            int i = it * 256 + t;            // half2 index, 8192 total
            int lr = i >> 6, lc = (i & 63) << 1;
            float v0 = fmaxf(stg[lr * LDS_ + lc]     + bias[nBase + lc],     0.f);
            float v1 = fmaxf(stg[lr * LDS_ + lc + 1] + bias[nBase + lc + 1], 0.f);
            __half h0 = __float2half_rn(v0), h1 = __float2half_rn(v1);
            __half l0 = __float2half_rn(v0 - __half2float(h0));
            __half l1 = __float2half_rn(v1 - __half2float(h1));
            size_t o = (size_t)(mBase + lr) * Nout + nBase + lc;
            *(__half2*)(outh + o) = __halves2half2(h0, h1);
            *(__half2*)(outl + o) = __halves2half2(l0, l1);
        }
    } else {
#pragma unroll
        for (int it = 0; it < 64; it++) {
            int i = it * 256 + t;            // f32 index, 16384 total
            int lr = i >> 7, lc = i & 127;
            float v = stg[lr * LDS_ + lc] + bias[nBase + lc];
            outf[(size_t)(mBase + lr) * Nout + nBase + lc] = fmaxf(v, 0.f);
        }
    }
}

// ---------------- layer 3 matvec + sigmoid + CAM ----------------
__global__ void att_kernel(const float* __restrict__ w3, const float* __restrict__ b3,
                           const float* __restrict__ cam, float* __restrict__ att_out)
{
    int warp = threadIdx.x >> 5;
    int lane = threadIdx.x & 31;
    int p = blockIdx.x * 8 + warp;
    const float* rowp = g_h2 + (size_t)p * N2;
    float s = 0.f;
#pragma unroll
    for (int j = 0; j < N2; j += 32) s = fmaf(rowp[j + lane], w3[j + lane], s);
#pragma unroll
    for (int off = 16; off; off >>= 1)
        s += __shfl_down_sync(0xffffffffu, s, off);
    if (lane == 0) {
        float v = 1.f / (1.f + expf(-(s + b3[0])));
        float a = (v + cam[p]) * 0.5f;
        g_att[p] = a;
        att_out[p] = a;
    }
}

// ---------------- peak picking ----------------
__global__ void peaks_kernel(float* __restrict__ coords_out)
{
    __shared__ float smv[1024];
    __shared__ float rv[8];
    __shared__ int   ri[8];
    __shared__ int   s_fy, s_fx;

    const int b = blockIdx.x;
    const int t = threadIdx.x;

    for (int i = t; i < 1024; i += 256) smv[i] = g_att[b * 1024 + i];
    __syncthreads();

    for (int k = 0; k < NREG; k++) {
        float best = -1.f;
        int bi = 1 << 30;
        for (int i = t; i < 1024; i += 256) {
            float v = smv[i];
            if (v > best) { best = v; bi = i; }
        }
#pragma unroll
        for (int off = 16; off; off >>= 1) {
            float ov = __shfl_down_sync(0xffffffffu, best, off);
            int   oi = __shfl_down_sync(0xffffffffu, bi, off);
            if (ov > best || (ov == best && oi < bi)) { best = ov; bi = oi; }
        }
        if ((t & 31) == 0) { rv[t >> 5] = best; ri[t >> 5] = bi; }
        __syncthreads();
        if (t == 0) {
            for (int w = 1; w < 8; w++)
                if (rv[w] > best || (rv[w] == best && ri[w] < bi)) { best = rv[w]; bi = ri[w]; }
            int fy = bi >> 5, fx = bi & 31;
            if (!(best > 0.f)) { fy = 16; fx = 16; }
            int y1 = min(max(fy * 16 - (RS / 2), 0), IMG - RS);
            int x1 = min(max(fx * 16 - (RS / 2), 0), IMG - RS);
            int r = b * NREG + k;
            g_xy[r * 2 + 0] = y1;
            g_xy[r * 2 + 1] = x1;
            float* cp = coords_out + r * 4;
            cp[0] = (float)x1;
            cp[1] = (float)y1;
            cp[2] = (float)(x1 + RS);
            cp[3] = (float)(y1 + RS);
            s_fy = fy; s_fx = fx;
        }
        __syncthreads();
        int fy = s_fy, fx = s_fx;
        for (int i = t; i < 1024; i += 256) {
            int y = i >> 5, x = i & 31;
            if (abs(y - fy) <= 5 && abs(x - fx) <= 5) smv[i] = 0.f;
        }
        __syncthreads();
    }
}

// ---------------- region crops ----------------
__global__ void crop_kernel(const float* __restrict__ orig, float* __restrict__ out)
{
    const int r = blockIdx.y;
    const int b = r / NREG;
    const int y1 = g_xy[r * 2 + 0];
    const int x1 = g_xy[r * 2 + 1];

    int idx = blockIdx.x * blockDim.x + threadIdx.x;
    int col4 = idx % 96;
    int tmp  = idx / 96;
    int rrow = tmp % RS;
    int c    = tmp / RS;

    const float* src = orig + (((size_t)(b * 3 + c) * IMG) + (y1 + rrow)) * IMG + x1;
    float4 v = *((const float4*)src + col4);
    float4* dst = (float4*)(out + (size_t)r * (3 * RS * RS)) + idx;
    *dst = v;
}

// ---------------- launch ----------------
extern "C" void kernel_launch(void* const* d_in, const int* in_sizes, int n_in,
                              void* d_out, int out_size)
{
    const float* features = (const float*)d_in[0];
    const float* cam      = (const float*)d_in[1];
    const float* original = (const float*)d_in[2];
    const float* w1 = (const float*)d_in[3];
    const float* b1 = (const float*)d_in[4];
    const float* w2 = (const float*)d_in[5];
    const float* b2 = (const float*)d_in[6];
    const float* w3 = (const float*)d_in[7];
    const float* b3 = (const float*)d_in[8];

    float* out = (float*)d_out;
    const size_t regions_elems = (size_t)B_ * NREG * 3 * RS * RS;
    float* coords_out = out + regions_elems;
    float* att_out    = coords_out + (size_t)B_ * NREG * 4;

    __half *a1h, *a1l, *h1h, *h1l, *w1h, *w1l, *w2h, *w2l;
    float *h2;
    cudaGetSymbolAddress((void**)&a1h, g_a1h);
    cudaGetSymbolAddress((void**)&a1l, g_a1l);
    cudaGetSymbolAddress((void**)&h1h, g_h1h);
    cudaGetSymbolAddress((void**)&h1l, g_h1l);
    cudaGetSymbolAddress((void**)&w1h, g_w1h);
    cudaGetSymbolAddress((void**)&w1l, g_w1l);
    cudaGetSymbolAddress((void**)&w2h, g_w2h);
    cudaGetSymbolAddress((void**)&w2l, g_w2l);
    cudaGetSymbolAddress((void**)&h2,  g_h2);

    cudaFuncSetAttribute(gemm_hmma<true>,  cudaFuncAttributeMaxDynamicSharedMemorySize, SMEM_DYN);
    cudaFuncSetAttribute(gemm_hmma<false>, cudaFuncAttributeMaxDynamicSharedMemorySize, SMEM_DYN);

    conv_feat<<<dim3(32, 32, 32), 256>>>(features);
    conv_w<<<(N1 * C1 + 255) / 256, 256>>>(w1, w1h, w1l, N1 * C1);
    conv_w<<<(N2 * N1 + 255) / 256, 256>>>(w2, w2h, w2l, N2 * N1);

    // GEMM1: relu(features x w1^T + b1) -> h1 (fp16 split out)
    gemm_hmma<true><<<dim3(N1 / 128, NPIX / 128), 256, SMEM_DYN>>>(
        a1h, a1l, w1h, w1l, b1, C1, N1, h1h, h1l, nullptr);
    // GEMM2: relu(h1 x w2^T + b2) -> h2 (f32 out)
    gemm_hmma<false><<<dim3(N2 / 128, NPIX / 128), 256, SMEM_DYN>>>(
        h1h, h1l, w2h, w2l, b2, N1, N2, nullptr, nullptr, h2);

    att_kernel<<<NPIX / 8, 256>>>(w3, b3, cam, att_out);
    peaks_kernel<<<B_, 256>>>(coords_out);
    crop_kernel<<<dim3(432, B_ * NREG), 256>>>(original, out);
}

// round 8
// speedup vs baseline: 2.2003x; 1.0568x over previous
#include <cuda_runtime.h>
#include <cuda_fp16.h>
#include <mma.h>
#include <cstdint>
#include <math.h>

using namespace nvcuda;

#define B_    32
#define C1    1024
#define N1    512
#define N2    256
#define HW    1024
#define NPIX  (B_*HW)
#define IMG   512
#define RS    384
#define NREG  3

// ---------------- static device scratch ----------------
__device__ __align__(16) __half g_a1h[(size_t)NPIX * C1];
__device__ __align__(16) __half g_a1l[(size_t)NPIX * C1];
__device__ __align__(16) __half g_h1h[(size_t)NPIX * N1];
__device__ __align__(16) __half g_h1l[(size_t)NPIX * N1];
__device__ __align__(16) __half g_w1h[N1 * C1];
__device__ __align__(16) __half g_w1l[N1 * C1];
__device__ __align__(16) __half g_w2h[N2 * N1];
__device__ __align__(16) __half g_w2l[N2 * N1];
__device__ float g_part[2][NPIX];
__device__ float g_att[NPIX];
__device__ int   g_xy[B_ * NREG * 2];

// ---------------- PTX helpers ----------------
__device__ __forceinline__ uint32_t smem_u32(const void* p) {
    uint32_t a;
    asm("{ .reg .u64 t; cvta.to.shared.u64 t, %1; cvt.u32.u64 %0, t; }" : "=r"(a) : "l"(p));
    return a;
}
__device__ __forceinline__ void cp16(uint32_t dst, const void* src) {
    asm volatile("cp.async.cg.shared.global [%0], [%1], 16;" :: "r"(dst), "l"(src));
}
__device__ __forceinline__ void cp_commit() { asm volatile("cp.async.commit_group;" ::: "memory"); }
template<int N> __device__ __forceinline__ void cp_wait() { asm volatile("cp.async.wait_group %0;" :: "n"(N) : "memory"); }

// ---------------- prep: features transpose + fp16 split ----------------
__global__ void conv_feat(const float* __restrict__ f) {
    __shared__ float tile[32][33];
    int b = blockIdx.z, k0 = blockIdx.x * 32, hw0 = blockIdx.y * 32;
    int tx = threadIdx.x & 31, ty = threadIdx.x >> 5;   // 32 x 8
    const float* src = f + ((size_t)b << 20) + (size_t)k0 * 1024 + hw0;
#pragma unroll
    for (int r = 0; r < 4; r++)
        tile[ty + r * 8][tx] = src[(size_t)(ty + r * 8) * 1024 + tx];
    __syncthreads();
#pragma unroll
    for (int r = 0; r < 4; r++) {
        int hw = ty + r * 8;
        float v = tile[tx][hw];
        size_t o = (((size_t)b << 10) + hw0 + hw) * 1024 + k0 + tx;
        __half h = __float2half_rn(v);
        g_a1h[o] = h;
        g_a1l[o] = __float2half_rn(v - __half2float(h));
    }
}

__global__ void conv_w(const float* __restrict__ w, __half* __restrict__ oh,
                       __half* __restrict__ ol, int n) {
    int i = blockIdx.x * 256 + threadIdx.x;
    if (i < n) {
        float v = w[i];
        __half h = __float2half_rn(v);
        oh[i] = h;
        ol[i] = __float2half_rn(v - __half2float(h));
    }
}

// ---------------- wmma GEMM: C = relu(A*W^T + b), 3-term fp16 split ----------------
// CTA tile 128x128, 256 threads (8 warps 4x2, warp tile 32x64), BK=64, 3 stages.
#define LDH     72                 // 64 + 8 halves pad (144 B row stride)
#define ATILE_B (128*LDH*2)        // 18432
#define STG_B   (2*ATILE_B)        // 36864 per stage (A + B)
#define LDS_    132
#define SMEM_DYN (3*STG_B)         // 110592

// FINAL=0: write relu result split to outh/outl. FINAL=1: fused layer3 partial dot.
template<bool FINAL>
__global__ __launch_bounds__(256, 2)
void gemm_hmma(const __half* __restrict__ a_h, const __half* __restrict__ a_l,
               const __half* __restrict__ b_h, const __half* __restrict__ b_l,
               const float* __restrict__ bias, int K, int Nout,
               __half* __restrict__ outh, __half* __restrict__ outl,
               const float* __restrict__ w3, float* __restrict__ part)
{
    extern __shared__ char sm[];
    __shared__ float s_w3[128];
    const int t = threadIdx.x;
    const int warp = t >> 5;
    const int lane = t & 31;
    const int warpM = warp >> 1, warpN = warp & 1;   // 4 x 2 warps, each 32 x 64
    const int mBase = blockIdx.y * 128, nBase = blockIdx.x * 128;

    const int KC  = K >> 6;
    const int NIT = 3 * KC;

    const __half* Ap[3] = {a_h, a_l, a_h};
    const __half* Bp[3] = {b_h, b_h, b_l};

    const uint32_t sbase = smem_u32(sm);

    if (FINAL && t < 128) s_w3[t] = w3[nBase + t];

    wmma::fragment<wmma::accumulator, 16, 16, 16, float> acc[2][4];
#pragma unroll
    for (int i = 0; i < 2; i++)
#pragma unroll
        for (int j = 0; j < 4; j++)
            wmma::fill_fragment(acc[i][j], 0.f);

    // per stage: A = 128 rows x 64 halves = 1024 16B-chunks; B same.
    // 256 threads -> each issues 4 chunks for A and 4 for B.
    auto issue = [&](int kk) {
        const int term = kk / KC;
        const int kc = (kk % KC) << 6;
        const int s = kk % 3;
        const __half* At = Ap[term];
        const __half* Bt = Bp[term];
#pragma unroll
        for (int u = 0; u < 4; u++) {
            int i = u * 256 + t;             // 0..1023
            int row = i >> 3, ch = i & 7;
            uint32_t off = (uint32_t)(row * LDH + ch * 8) * 2;
            cp16(sbase + s * STG_B + off,
                 At + (size_t)(mBase + row) * K + kc + ch * 8);
            cp16(sbase + s * STG_B + ATILE_B + off,
                 Bt + (size_t)(nBase + row) * K + kc + ch * 8);
        }
    };

    issue(0); cp_commit();
    issue(1); cp_commit();

    for (int kk = 0; kk < NIT; kk++) {
        const int s = kk % 3;
        cp_wait<1>();
        __syncthreads();
        const __half* As = (const __half*)(sm + s * STG_B);
        const __half* Bs = (const __half*)(sm + s * STG_B + ATILE_B);

        wmma::fragment<wmma::matrix_a, 16, 16, 16, __half, wmma::row_major> af[2];
#pragma unroll
        for (int k16 = 0; k16 < 4; k16++) {
            wmma::load_matrix_sync(af[0], As + (warpM * 32) * LDH + k16 * 16, LDH);
            wmma::load_matrix_sync(af[1], As + (warpM * 32 + 16) * LDH + k16 * 16, LDH);
#pragma unroll
            for (int j = 0; j < 4; j++) {
                wmma::fragment<wmma::matrix_b, 16, 16, 16, __half, wmma::col_major> bf;
                wmma::load_matrix_sync(bf, Bs + (warpN * 64 + j * 16) * LDH + k16 * 16, LDH);
                wmma::mma_sync(acc[0][j], af[0], bf, acc[0][j]);
                wmma::mma_sync(acc[1][j], af[1], bf, acc[1][j]);
            }
        }
        if (kk + 2 < NIT) issue(kk + 2);
        cp_commit();
    }

    cp_wait<0>();
    __syncthreads();
    float* stg = (float*)sm;
#pragma unroll
    for (int i = 0; i < 2; i++)
#pragma unroll
        for (int j = 0; j < 4; j++)
            wmma::store_matrix_sync(stg + (warpM * 32 + i * 16) * LDS_ + warpN * 64 + j * 16,
                                    acc[i][j], LDS_, wmma::mem_row_major);
    __syncthreads();

    if (!FINAL) {
#pragma unroll
        for (int it = 0; it < 32; it++) {
            int i = it * 256 + t;            // half2 index, 8192 total
            int lr = i >> 6, lc = (i & 63) << 1;
            float v0 = fmaxf(stg[lr * LDS_ + lc]     + bias[nBase + lc],     0.f);
            float v1 = fmaxf(stg[lr * LDS_ + lc + 1] + bias[nBase + lc + 1], 0.f);
            __half h0 = __float2half_rn(v0), h1 = __float2half_rn(v1);
            __half l0 = __float2half_rn(v0 - __half2float(h0));
            __half l1 = __float2half_rn(v1 - __half2float(h1));
            size_t o = (size_t)(mBase + lr) * Nout + nBase + lc;
            *(__half2*)(outh + o) = __halves2half2(h0, h1);
            *(__half2*)(outl + o) = __halves2half2(l0, l1);
        }
    } else {
        // fused layer-3 partial dot: each warp handles 16 rows of 128 cols
#pragma unroll
        for (int rr = 0; rr < 16; rr++) {
            int row = warp * 16 + rr;
            float s = 0.f;
#pragma unroll
            for (int q = 0; q < 4; q++) {
                int c = q * 32 + lane;
                float v = fmaxf(stg[row * LDS_ + c] + bias[nBase + c], 0.f);
                s = fmaf(v, s_w3[c], s);
            }
#pragma unroll
            for (int off = 16; off; off >>= 1)
                s += __shfl_down_sync(0xffffffffu, s, off);
            if (lane == 0)
                part[(size_t)blockIdx.x * NPIX + mBase + row] = s;
        }
    }
}

// ---------------- finalize att: sum partials + sigmoid + CAM ----------------
__global__ void finalize_att(const float* __restrict__ b3, const float* __restrict__ cam,
                             float* __restrict__ att_out)
{
    int p = blockIdx.x * 256 + threadIdx.x;
    float s = g_part[0][p] + g_part[1][p] + b3[0];
    float v = 1.f / (1.f + expf(-s));
    float a = (v + cam[p]) * 0.5f;
    g_att[p] = a;
    att_out[p] = a;
}

// ---------------- peak picking ----------------
__global__ void peaks_kernel(float* __restrict__ coords_out)
{
    __shared__ float smv[1024];
    __shared__ float rv[8];
    __shared__ int   ri[8];
    __shared__ int   s_fy, s_fx;

    const int b = blockIdx.x;
    const int t = threadIdx.x;

    for (int i = t; i < 1024; i += 256) smv[i] = g_att[b * 1024 + i];
    __syncthreads();

    for (int k = 0; k < NREG; k++) {
        float best = -1.f;
        int bi = 1 << 30;
        for (int i = t; i < 1024; i += 256) {
            float v = smv[i];
            if (v > best) { best = v; bi = i; }
        }
#pragma unroll
        for (int off = 16; off; off >>= 1) {
            float ov = __shfl_down_sync(0xffffffffu, best, off);
            int   oi = __shfl_down_sync(0xffffffffu, bi, off);
            if (ov > best || (ov == best && oi < bi)) { best = ov; bi = oi; }
        }
        if ((t & 31) == 0) { rv[t >> 5] = best; ri[t >> 5] = bi; }
        __syncthreads();
        if (t == 0) {
            for (int w = 1; w < 8; w++)
                if (rv[w] > best || (rv[w] == best && ri[w] < bi)) { best = rv[w]; bi = ri[w]; }
            int fy = bi >> 5, fx = bi & 31;
            if (!(best > 0.f)) { fy = 16; fx = 16; }
            int y1 = min(max(fy * 16 - (RS / 2), 0), IMG - RS);
            int x1 = min(max(fx * 16 - (RS / 2), 0), IMG - RS);
            int r = b * NREG + k;
            g_xy[r * 2 + 0] = y1;
            g_xy[r * 2 + 1] = x1;
            float* cp = coords_out + r * 4;
            cp[0] = (float)x1;
            cp[1] = (float)y1;
            cp[2] = (float)(x1 + RS);
            cp[3] = (float)(y1 + RS);
            s_fy = fy; s_fx = fx;
        }
        __syncthreads();
        int fy = s_fy, fx = s_fx;
        for (int i = t; i < 1024; i += 256) {
            int y = i >> 5, x = i & 31;
            if (abs(y - fy) <= 5 && abs(x - fx) <= 5) smv[i] = 0.f;
        }
        __syncthreads();
    }
}

// ---------------- region crops ----------------
__global__ void crop_kernel(const float* __restrict__ orig, float* __restrict__ out)
{
    const int r = blockIdx.y;
    const int b = r / NREG;
    const int y1 = g_xy[r * 2 + 0];
    const int x1 = g_xy[r * 2 + 1];

    int idx = blockIdx.x * blockDim.x + threadIdx.x;
    int col4 = idx % 96;
    int tmp  = idx / 96;
    int rrow = tmp % RS;
    int c    = tmp / RS;

    const float* src = orig + (((size_t)(b * 3 + c) * IMG) + (y1 + rrow)) * IMG + x1;
    float4 v = *((const float4*)src + col4);
    float4* dst = (float4*)(out + (size_t)r * (3 * RS * RS)) + idx;
    *dst = v;
}

// ---------------- launch ----------------
extern "C" void kernel_launch(void* const* d_in, const int* in_sizes, int n_in,
                              void* d_out, int out_size)
{
    const float* features = (const float*)d_in[0];
    const float* cam      = (const float*)d_in[1];
    const float* original = (const float*)d_in[2];
    const float* w1 = (const float*)d_in[3];
    const float* b1 = (const float*)d_in[4];
    const float* w2 = (const float*)d_in[5];
    const float* b2 = (const float*)d_in[6];
    const float* w3 = (const float*)d_in[7];
    const float* b3 = (const float*)d_in[8];

    float* out = (float*)d_out;
    const size_t regions_elems = (size_t)B_ * NREG * 3 * RS * RS;
    float* coords_out = out + regions_elems;
    float* att_out    = coords_out + (size_t)B_ * NREG * 4;

    __half *a1h, *a1l, *h1h, *h1l, *w1h, *w1l, *w2h, *w2l;
    float *part;
    cudaGetSymbolAddress((void**)&a1h, g_a1h);
    cudaGetSymbolAddress((void**)&a1l, g_a1l);
    cudaGetSymbolAddress((void**)&h1h, g_h1h);
    cudaGetSymbolAddress((void**)&h1l, g_h1l);
    cudaGetSymbolAddress((void**)&w1h, g_w1h);
    cudaGetSymbolAddress((void**)&w1l, g_w1l);
    cudaGetSymbolAddress((void**)&w2h, g_w2h);
    cudaGetSymbolAddress((void**)&w2l, g_w2l);
    cudaGetSymbolAddress((void**)&part, g_part);

    cudaFuncSetAttribute(gemm_hmma<false>, cudaFuncAttributeMaxDynamicSharedMemorySize, SMEM_DYN);
    cudaFuncSetAttribute(gemm_hmma<true>,  cudaFuncAttributeMaxDynamicSharedMemorySize, SMEM_DYN);

    conv_feat<<<dim3(32, 32, 32), 256>>>(features);
    conv_w<<<(N1 * C1 + 255) / 256, 256>>>(w1, w1h, w1l, N1 * C1);
    conv_w<<<(N2 * N1 + 255) / 256, 256>>>(w2, w2h, w2l, N2 * N1);

    // GEMM1: relu(features x w1^T + b1) -> h1 (fp16 split out)
    gemm_hmma<false><<<dim3(N1 / 128, NPIX / 128), 256, SMEM_DYN>>>(
        a1h, a1l, w1h, w1l, b1, C1, N1, h1h, h1l, nullptr, nullptr);
    // GEMM2 + fused layer3 partial dot
    gemm_hmma<true><<<dim3(N2 / 128, NPIX / 128), 256, SMEM_DYN>>>(
        h1h, h1l, w2h, w2l, b2, N1, N2, nullptr, nullptr, w3, part);

    finalize_att<<<NPIX / 256, 256>>>(b3, cam, att_out);
    peaks_kernel<<<B_, 256>>>(coords_out);
    crop_kernel<<<dim3(432, B_ * NREG), 256>>>(original, out);
}

// round 9
// speedup vs baseline: 2.2590x; 1.0267x over previous
#include <cuda_runtime.h>
#include <cuda_fp16.h>
#include <mma.h>
#include <cstdint>
#include <math.h>

using namespace nvcuda;

#define B_    32
#define C1    1024
#define N1    512
#define N2    256
#define HW    1024
#define NPIX  (B_*HW)
#define IMG   512
#define RS    384
#define NREG  3

// ---------------- static device scratch ----------------
__device__ __align__(16) __half g_a1h[(size_t)NPIX * C1];
__device__ __align__(16) __half g_a1l[(size_t)NPIX * C1];
__device__ __align__(16) __half g_h1h[(size_t)NPIX * N1];
__device__ __align__(16) __half g_h1l[(size_t)NPIX * N1];
__device__ __align__(16) __half g_w1h[N1 * C1];
__device__ __align__(16) __half g_w1l[N1 * C1];
__device__ __align__(16) __half g_w2h[N2 * N1];
__device__ __align__(16) __half g_w2l[N2 * N1];
__device__ float g_part[2][NPIX];
__device__ float g_att[NPIX];
__device__ int   g_xy[B_ * NREG * 2];

// ---------------- PTX helpers ----------------
__device__ __forceinline__ uint32_t smem_u32(const void* p) {
    uint32_t a;
    asm("{ .reg .u64 t; cvta.to.shared.u64 t, %1; cvt.u32.u64 %0, t; }" : "=r"(a) : "l"(p));
    return a;
}
__device__ __forceinline__ void cp16(uint32_t dst, const void* src) {
    asm volatile("cp.async.cg.shared.global [%0], [%1], 16;" :: "r"(dst), "l"(src));
}
__device__ __forceinline__ void cp_commit() { asm volatile("cp.async.commit_group;" ::: "memory"); }
template<int N> __device__ __forceinline__ void cp_wait() { asm volatile("cp.async.wait_group %0;" :: "n"(N) : "memory"); }

// ---------------- prep: features transpose + fp16 split ----------------
__global__ void conv_feat(const float* __restrict__ f) {
    __shared__ float tile[32][33];
    int b = blockIdx.z, k0 = blockIdx.x * 32, hw0 = blockIdx.y * 32;
    int tx = threadIdx.x & 31, ty = threadIdx.x >> 5;   // 32 x 8
    const float* src = f + ((size_t)b << 20) + (size_t)k0 * 1024 + hw0;
#pragma unroll
    for (int r = 0; r < 4; r++)
        tile[ty + r * 8][tx] = src[(size_t)(ty + r * 8) * 1024 + tx];
    __syncthreads();
#pragma unroll
    for (int r = 0; r < 4; r++) {
        int hw = ty + r * 8;
        float v = tile[tx][hw];
        size_t o = (((size_t)b << 10) + hw0 + hw) * 1024 + k0 + tx;
        __half h = __float2half_rn(v);
        g_a1h[o] = h;
        g_a1l[o] = __float2half_rn(v - __half2float(h));
    }
}

__global__ void conv_w(const float* __restrict__ w, __half* __restrict__ oh,
                       __half* __restrict__ ol, int n) {
    int i = blockIdx.x * 256 + threadIdx.x;
    if (i < n) {
        float v = w[i];
        __half h = __float2half_rn(v);
        oh[i] = h;
        ol[i] = __float2half_rn(v - __half2float(h));
    }
}

// ---------------- wmma GEMM: C = relu(A*W^T + b), 3-term fp16 split ----------------
// CTA tile 128x128, 256 threads (8 warps 4x2, warp tile 32x64), BK=64, 3 stages.
#define LDH     72                 // 64 + 8 halves pad (144 B row stride)
#define ATILE_B (128*LDH*2)        // 18432
#define STG_B   (2*ATILE_B)        // 36864 per stage (A + B)
#define LDS_    132
#define SMEM_DYN (3*STG_B)         // 110592

// FINAL=0: write relu result split to outh/outl. FINAL=1: fused layer3 partial dot.
template<int K, bool FINAL>
__global__ __launch_bounds__(256, 2)
void gemm_hmma(const __half* __restrict__ a_h, const __half* __restrict__ a_l,
               const __half* __restrict__ b_h, const __half* __restrict__ b_l,
               const float* __restrict__ bias, int Nout,
               __half* __restrict__ outh, __half* __restrict__ outl,
               const float* __restrict__ w3, float* __restrict__ part)
{
    extern __shared__ char sm[];
    __shared__ float s_w3[128];
    const int t = threadIdx.x;
    const int warp = t >> 5;
    const int lane = t & 31;
    const int warpM = warp >> 1, warpN = warp & 1;   // 4 x 2 warps, each 32 x 64
    const int mBase = blockIdx.y * 128, nBase = blockIdx.x * 128;

    constexpr int KC  = K >> 6;
    constexpr int NIT = 3 * KC;

    const __half* Ap[3] = {a_h, a_l, a_h};
    const __half* Bp[3] = {b_h, b_h, b_l};

    const uint32_t sbase = smem_u32(sm);

    if (FINAL && t < 128) s_w3[t] = w3[nBase + t];

    // precomputed 32-bit row offsets for the loader (4 chunks per operand)
    int offA[4], offB[4];
    uint32_t dstOff[4];
#pragma unroll
    for (int u = 0; u < 4; u++) {
        int i = u * 256 + t;             // 0..1023
        int row = i >> 3, ch = i & 7;
        offA[u] = (mBase + row) * K + ch * 8;
        offB[u] = (nBase + row) * K + ch * 8;
        dstOff[u] = (uint32_t)(row * LDH + ch * 8) * 2;
    }

    wmma::fragment<wmma::accumulator, 16, 16, 16, float> acc[2][4];
#pragma unroll
    for (int i = 0; i < 2; i++)
#pragma unroll
        for (int j = 0; j < 4; j++)
            wmma::fill_fragment(acc[i][j], 0.f);

    auto issue = [&](int kk) {
        const int term = kk / KC;
        const int kc = (kk % KC) << 6;
        const int s = kk % 3;
        const __half* At = Ap[term] + kc;
        const __half* Bt = Bp[term] + kc;
        const uint32_t sA = sbase + s * STG_B;
        const uint32_t sB = sA + ATILE_B;
#pragma unroll
        for (int u = 0; u < 4; u++) {
            cp16(sA + dstOff[u], At + offA[u]);
            cp16(sB + dstOff[u], Bt + offB[u]);
        }
    };

    issue(0); cp_commit();
    issue(1); cp_commit();

#pragma unroll 3
    for (int kk = 0; kk < NIT; kk++) {
        const int s = kk % 3;
        cp_wait<1>();
        __syncthreads();
        const __half* As = (const __half*)(sm + s * STG_B);
        const __half* Bs = (const __half*)(sm + s * STG_B + ATILE_B);
        const __half* Aw = As + (warpM * 32) * LDH;
        const __half* Bw = Bs + (warpN * 64) * LDH;

        wmma::fragment<wmma::matrix_a, 16, 16, 16, __half, wmma::row_major> af[2];
        wmma::fragment<wmma::matrix_b, 16, 16, 16, __half, wmma::col_major> bf[2];
#pragma unroll
        for (int k16 = 0; k16 < 4; k16++) {
            wmma::load_matrix_sync(af[0], Aw + k16 * 16, LDH);
            wmma::load_matrix_sync(af[1], Aw + 16 * LDH + k16 * 16, LDH);
            wmma::load_matrix_sync(bf[0], Bw + k16 * 16, LDH);
            int cur = 0;
#pragma unroll
            for (int j = 0; j < 4; j++) {
                if (j < 3)
                    wmma::load_matrix_sync(bf[cur ^ 1], Bw + (j + 1) * 16 * LDH + k16 * 16, LDH);
                wmma::mma_sync(acc[0][j], af[0], bf[cur], acc[0][j]);
                wmma::mma_sync(acc[1][j], af[1], bf[cur], acc[1][j]);
                cur ^= 1;
            }
        }
        if (kk + 2 < NIT) issue(kk + 2);
        cp_commit();
    }

    cp_wait<0>();
    __syncthreads();
    float* stg = (float*)sm;
#pragma unroll
    for (int i = 0; i < 2; i++)
#pragma unroll
        for (int j = 0; j < 4; j++)
            wmma::store_matrix_sync(stg + (warpM * 32 + i * 16) * LDS_ + warpN * 64 + j * 16,
                                    acc[i][j], LDS_, wmma::mem_row_major);
    __syncthreads();

    if (!FINAL) {
#pragma unroll
        for (int it = 0; it < 32; it++) {
            int i = it * 256 + t;            // half2 index, 8192 total
            int lr = i >> 6, lc = (i & 63) << 1;
            float v0 = fmaxf(stg[lr * LDS_ + lc]     + bias[nBase + lc],     0.f);
            float v1 = fmaxf(stg[lr * LDS_ + lc + 1] + bias[nBase + lc + 1], 0.f);
            __half h0 = __float2half_rn(v0), h1 = __float2half_rn(v1);
            __half l0 = __float2half_rn(v0 - __half2float(h0));
            __half l1 = __float2half_rn(v1 - __half2float(h1));
            size_t o = (size_t)(mBase + lr) * Nout + nBase + lc;
            *(__half2*)(outh + o) = __halves2half2(h0, h1);
            *(__half2*)(outl + o) = __halves2half2(l0, l1);
        }
    } else {
        // fused layer-3 partial dot: each warp handles 16 rows of 128 cols
#pragma unroll
        for (int rr = 0; rr < 16; rr++) {
            int row = warp * 16 + rr;
            float s = 0.f;
#pragma unroll
            for (int q = 0; q < 4; q++) {
                int c = q * 32 + lane;
                float v = fmaxf(stg[row * LDS_ + c] + bias[nBase + c], 0.f);
                s = fmaf(v, s_w3[c], s);
            }
#pragma unroll
            for (int off = 16; off; off >>= 1)
                s += __shfl_down_sync(0xffffffffu, s, off);
            if (lane == 0)
                part[(size_t)blockIdx.x * NPIX + mBase + row] = s;
        }
    }
}

// ---------------- finalize att: sum partials + sigmoid + CAM ----------------
__global__ void finalize_att(const float* __restrict__ b3, const float* __restrict__ cam,
                             float* __restrict__ att_out)
{
    int p = blockIdx.x * 256 + threadIdx.x;
    float s = g_part[0][p] + g_part[1][p] + b3[0];
    float v = 1.f / (1.f + expf(-s));
    float a = (v + cam[p]) * 0.5f;
    g_att[p] = a;
    att_out[p] = a;
}

// ---------------- peak picking ----------------
__global__ void peaks_kernel(float* __restrict__ coords_out)
{
    __shared__ float smv[1024];
    __shared__ float rv[8];
    __shared__ int   ri[8];
    __shared__ int   s_fy, s_fx;

    const int b = blockIdx.x;
    const int t = threadIdx.x;

    for (int i = t; i < 1024; i += 256) smv[i] = g_att[b * 1024 + i];
    __syncthreads();

    for (int k = 0; k < NREG; k++) {
        float best = -1.f;
        int bi = 1 << 30;
        for (int i = t; i < 1024; i += 256) {
            float v = smv[i];
            if (v > best) { best = v; bi = i; }
        }
#pragma unroll
        for (int off = 16; off; off >>= 1) {
            float ov = __shfl_down_sync(0xffffffffu, best, off);
            int   oi = __shfl_down_sync(0xffffffffu, bi, off);
            if (ov > best || (ov == best && oi < bi)) { best = ov; bi = oi; }
        }
        if ((t & 31) == 0) { rv[t >> 5] = best; ri[t >> 5] = bi; }
        __syncthreads();
        if (t == 0) {
            for (int w = 1; w < 8; w++)
                if (rv[w] > best || (rv[w] == best && ri[w] < bi)) { best = rv[w]; bi = ri[w]; }
            int fy = bi >> 5, fx = bi & 31;
            if (!(best > 0.f)) { fy = 16; fx = 16; }
            int y1 = min(max(fy * 16 - (RS / 2), 0), IMG - RS);
            int x1 = min(max(fx * 16 - (RS / 2), 0), IMG - RS);
            int r = b * NREG + k;
            g_xy[r * 2 + 0] = y1;
            g_xy[r * 2 + 1] = x1;
            float* cp = coords_out + r * 4;
            cp[0] = (float)x1;
            cp[1] = (float)y1;
            cp[2] = (float)(x1 + RS);
            cp[3] = (float)(y1 + RS);
            s_fy = fy; s_fx = fx;
        }
        __syncthreads();
        int fy = s_fy, fx = s_fx;
        for (int i = t; i < 1024; i += 256) {
            int y = i >> 5, x = i & 31;
            if (abs(y - fy) <= 5 && abs(x - fx) <= 5) smv[i] = 0.f;
        }
        __syncthreads();
    }
}

// ---------------- region crops ----------------
__global__ void crop_kernel(const float* __restrict__ orig, float* __restrict__ out)
{
    const int r = blockIdx.y;
    const int b = r / NREG;
    const int y1 = g_xy[r * 2 + 0];
    const int x1 = g_xy[r * 2 + 1];

    int idx = blockIdx.x * blockDim.x + threadIdx.x;
    int col4 = idx % 96;
    int tmp  = idx / 96;
    int rrow = tmp % RS;
    int c    = tmp / RS;

    const float* src = orig + (((size_t)(b * 3 + c) * IMG) + (y1 + rrow)) * IMG + x1;
    float4 v = *((const float4*)src + col4);
    float4* dst = (float4*)(out + (size_t)r * (3 * RS * RS)) + idx;
    *dst = v;
}

// ---------------- launch ----------------
extern "C" void kernel_launch(void* const* d_in, const int* in_sizes, int n_in,
                              void* d_out, int out_size)
{
    const float* features = (const float*)d_in[0];
    const float* cam      = (const float*)d_in[1];
    const float* original = (const float*)d_in[2];
    const float* w1 = (const float*)d_in[3];
    const float* b1 = (const float*)d_in[4];
    const float* w2 = (const float*)d_in[5];
    const float* b2 = (const float*)d_in[6];
    const float* w3 = (const float*)d_in[7];
    const float* b3 = (const float*)d_in[8];

    float* out = (float*)d_out;
    const size_t regions_elems = (size_t)B_ * NREG * 3 * RS * RS;
    float* coords_out = out + regions_elems;
    float* att_out    = coords_out + (size_t)B_ * NREG * 4;

    __half *a1h, *a1l, *h1h, *h1l, *w1h, *w1l, *w2h, *w2l;
    float *part;
    cudaGetSymbolAddress((void**)&a1h, g_a1h);
    cudaGetSymbolAddress((void**)&a1l, g_a1l);
    cudaGetSymbolAddress((void**)&h1h, g_h1h);
    cudaGetSymbolAddress((void**)&h1l, g_h1l);
    cudaGetSymbolAddress((void**)&w1h, g_w1h);
    cudaGetSymbolAddress((void**)&w1l, g_w1l);
    cudaGetSymbolAddress((void**)&w2h, g_w2h);
    cudaGetSymbolAddress((void**)&w2l, g_w2l);
    cudaGetSymbolAddress((void**)&part, g_part);

    cudaFuncSetAttribute(gemm_hmma<C1, false>, cudaFuncAttributeMaxDynamicSharedMemorySize, SMEM_DYN);
    cudaFuncSetAttribute(gemm_hmma<N1, true>,  cudaFuncAttributeMaxDynamicSharedMemorySize, SMEM_DYN);

    conv_feat<<<dim3(32, 32, 32), 256>>>(features);
    conv_w<<<(N1 * C1 + 255) / 256, 256>>>(w1, w1h, w1l, N1 * C1);
    conv_w<<<(N2 * N1 + 255) / 256, 256>>>(w2, w2h, w2l, N2 * N1);

    // GEMM1: relu(features x w1^T + b1) -> h1 (fp16 split out)
    gemm_hmma<C1, false><<<dim3(N1 / 128, NPIX / 128), 256, SMEM_DYN>>>(
        a1h, a1l, w1h, w1l, b1, N1, h1h, h1l, nullptr, nullptr);
    // GEMM2 + fused layer3 partial dot
    gemm_hmma<N1, true><<<dim3(N2 / 128, NPIX / 128), 256, SMEM_DYN>>>(
        h1h, h1l, w2h, w2l, b2, N2, nullptr, nullptr, w3, part);

    finalize_att<<<NPIX / 256, 256>>>(b3, cam, att_out);
    peaks_kernel<<<B_, 256>>>(coords_out);
    crop_kernel<<<dim3(432, B_ * NREG), 256>>>(original, out);
}